// round 14
// baseline (speedup 1.0000x reference)
#include <cuda_runtime.h>
#include <cuda_fp16.h>
#include <cstdint>
#include <math.h>

// ---------------- problem constants ----------------
constexpr int BSZ   = 2048;
constexpr int VIEWS = 2;
constexpr int DIM   = 512;
constexpr int NTOT  = BSZ * VIEWS;          // 4096
constexpr float TEMP = 0.07f;
constexpr float RSQRT2PI = 0.3989422804014327f;

// GEMM tiling (R11-proven): 128x128 CTA tile, 8 warps of 64x32, K-chunks of 64
constexpr int KC = 64;
constexpr int NCHUNK = DIM / KC;             // 8
constexpr int STAGE = 32768;                 // A 16K + B 16K per chunk
constexpr int NSTG = 3;
constexpr int DSMEM = NSTG * STAGE;          // 98304 B -> 2 CTAs/SM
constexpr int NTILES = 528;

// ---------------- device scratch --------------------
__device__ __align__(16) unsigned g_FA[8192 * 32 * 4];    // 4 MB
__device__ __align__(16) unsigned g_FB[16384 * 32 * 2];   // 4 MB
__device__ __align__(16) unsigned short g_dt [(size_t)BSZ * BSZ];   // delta[i][j], 8 MB
__device__ __align__(16) unsigned short g_dtT[(size_t)BSZ * BSZ];   // delta[j][i], 8 MB
__device__ unsigned g_pos[BSZ];              // (lower_bound(li) << 16) | last_index(<= li)
__device__ int g_cdf[257];                   // cdf[b] = #sorted labels < b/256
__device__ float g_S[BSZ];
__device__ float g_sorted[BSZ];
__device__ float g_u[NTOT];
__device__ float g_p[NTOT];
__device__ unsigned g_ctr;                   // k_main completion counter

// ---------------- PTX helpers -----------------------
__device__ __forceinline__ uint32_t smem_u32(const void* p) {
    uint32_t a;
    asm("{ .reg .u64 t; cvta.to.shared.u64 t, %1; cvt.u32.u64 %0, t; }" : "=r"(a) : "l"(p));
    return a;
}
__device__ __forceinline__ void cpa16(uint32_t d, const void* s) {
    asm volatile("cp.async.cg.shared.global [%0], [%1], 16;" :: "r"(d), "l"(s) : "memory");
}
#define CP_COMMIT() asm volatile("cp.async.commit_group;" ::: "memory")
#define CP_WAIT0()  asm volatile("cp.async.wait_group 0;" ::: "memory")
#define CP_WAIT1()  asm volatile("cp.async.wait_group 1;" ::: "memory")
__device__ __forceinline__ void mma_f16(float* c, const uint32_t* a, const uint32_t* b) {
    asm volatile("mma.sync.aligned.m16n8k16.row.col.f32.f16.f16.f32 "
        "{%0,%1,%2,%3}, {%4,%5,%6,%7}, {%8,%9}, {%0,%1,%2,%3};"
        : "+f"(c[0]), "+f"(c[1]), "+f"(c[2]), "+f"(c[3])
        : "r"(a[0]), "r"(a[1]), "r"(a[2]), "r"(a[3]), "r"(b[0]), "r"(b[1]));
}

// ---------------- K0: fp16 scatter (blocks 1..768) + sort/pos/cdf (block 0) --
__device__ __forceinline__ float ld_feat(const float* feats, int row, int col) {
    int b = row & (BSZ - 1), v = row >> 11;
    return feats[(size_t)((b << 1) | v) * DIM + col];
}
__device__ __forceinline__ unsigned pack2(const float* feats, int row, int col) {
    __half2 h = __floats2half2_rn(ld_feat(feats, row, col), ld_feat(feats, row, col + 1));
    return *(unsigned*)&h;
}
__global__ __launch_bounds__(1024) void k_prep(const float* __restrict__ feats,
                                               const float* __restrict__ labels) {
    __shared__ float s[BSZ];
    if (blockIdx.x == 0) {
        // ---- label sort (hybrid bitonic) + positions + CDF ----
        int tid = threadIdx.x;
        int lane = tid & 31, warp = tid >> 5;
        int base = warp * 64;
        int i0 = base + lane, i1 = i0 + 32;
        s[tid] = labels[tid]; s[tid + 1024] = labels[tid + 1024];
        __syncthreads();
        {
            float v0 = s[i0], v1 = s[i1];
#pragma unroll
            for (int k = 2; k <= 64; k <<= 1) {
#pragma unroll
                for (int j = k >> 1; j >= 1; j >>= 1) {
                    if (j == 32) {
                        bool up = ((i0 & k) == 0);
                        float lo = fminf(v0, v1), hi = fmaxf(v0, v1);
                        v0 = up ? lo : hi; v1 = up ? hi : lo;
                    } else {
                        bool up0 = ((i0 & k) == 0), up1 = ((i1 & k) == 0);
                        bool upper = (lane & j) != 0;
                        float p0 = __shfl_xor_sync(0xffffffffu, v0, j);
                        float p1 = __shfl_xor_sync(0xffffffffu, v1, j);
                        v0 = (up0 ^ upper) ? fminf(v0, p0) : fmaxf(v0, p0);
                        v1 = (up1 ^ upper) ? fminf(v1, p1) : fmaxf(v1, p1);
                    }
                }
            }
            s[i0] = v0; s[i1] = v1;
        }
        __syncthreads();
        for (int k = 128; k <= 2048; k <<= 1) {
            for (int j = k >> 1; j >= 64; j >>= 1) {
                for (int i = tid; i < BSZ; i += 1024) {
                    int ixj = i ^ j;
                    if (ixj > i) {
                        bool up = ((i & k) == 0);
                        float a = s[i], b = s[ixj];
                        if ((a > b) == up) { s[i] = b; s[ixj] = a; }
                    }
                }
                __syncthreads();
            }
            {
                float v0 = s[i0], v1 = s[i1];
                bool up = ((i0 & k) == 0);
                float lo = fminf(v0, v1), hi = fmaxf(v0, v1);
                v0 = up ? lo : hi; v1 = up ? hi : lo;
#pragma unroll
                for (int j = 16; j >= 1; j >>= 1) {
                    bool upper = (lane & j) != 0;
                    float p0 = __shfl_xor_sync(0xffffffffu, v0, j);
                    float p1 = __shfl_xor_sync(0xffffffffu, v1, j);
                    v0 = (up ^ upper) ? fminf(v0, p0) : fmaxf(v0, p0);
                    v1 = (up ^ upper) ? fminf(v1, p1) : fmaxf(v1, p1);
                }
                s[i0] = v0; s[i1] = v1;
            }
            __syncthreads();
        }
        g_sorted[tid] = s[tid]; g_sorted[tid + 1024] = s[tid + 1024];
        for (int ib = tid; ib < BSZ; ib += 1024) {
            float li = labels[ib];
            int p = 0, q = 0;
#pragma unroll
            for (int st = 2048; st; st >>= 1) {
                int np = p + st, nq = q + st;
                if (np <= BSZ && s[np - 1] <  li) p = np;
                if (nq <= BSZ && s[nq - 1] <= li) q = nq;
            }
            g_pos[ib] = ((unsigned)p << 16) | (unsigned)(q - 1);
        }
        if (tid <= 256) {
            float thr = (float)tid * 0.00390625f;
            int q = 0;
#pragma unroll
            for (int st = 2048; st; st >>= 1) {
                int nq = q + st;
                if (nq <= BSZ && s[nq - 1] < thr) q = nq;
            }
            g_cdf[tid] = q;
        }
        return;
    }
    // ---- fragment-major fp16 scatter (blocks 1..768) ----
    if (blockIdx.x == 1 && threadIdx.x == 0) g_ctr = 0;   // reset completion counter
    int tid = (blockIdx.x - 1) * 1024 + threadIdx.x;      // 0..786431
    if (tid < NTOT) { g_u[tid] = 0.f; g_p[tid] = 0.f; }
    int gw = tid >> 5;
    int l  = tid & 31;
    int g  = l >> 2, tg = l & 3;
    if (gw < 8192) {
        int sA = gw & 1, t = (gw >> 1) & 7, ch = (gw >> 4) & 15, rg = gw >> 8;
        int R = rg * 128 + t * 16 + g;
        int C = ch * 32 + sA * 16 + tg * 2;
        uint4 o;
        o.x = pack2(feats, R,     C);
        o.y = pack2(feats, R + 8, C);
        o.z = pack2(feats, R,     C + 8);
        o.w = pack2(feats, R + 8, C + 8);
        ((uint4*)g_FA)[(size_t)gw * 32 + l] = o;
    } else {
        int w2 = gw - 8192;
        int sB = w2 & 1, n8 = (w2 >> 1) & 15, ch = (w2 >> 5) & 15, ng = w2 >> 9;
        int J = ng * 128 + n8 * 8 + g;
        int K = ch * 32 + sB * 16 + tg * 2;
        uint2 o;
        o.x = pack2(feats, J, K);
        o.y = pack2(feats, J, K + 8);
        ((uint2*)g_FB)[(size_t)w2 * 32 + l] = o;
    }
}

// ---------------- K2: delta^T table, 2 rows per block + S row sums -----------
__global__ void k_tab(const float* __restrict__ labels) {
    __shared__ float s[BSZ];
    __shared__ int cdf[257];
    __shared__ float red[256];
    int tid = threadIdx.x;
    int jb0 = blockIdx.x * 2, jb1 = jb0 + 1;
    for (int m = tid; m < BSZ; m += 256) s[m] = g_sorted[m];
    if (tid < 256) cdf[tid] = g_cdf[tid];
    if (tid == 0)  cdf[256] = g_cdf[256];
    __syncthreads();
    float c0r = labels[jb0], c1r = labels[jb1];
    float rs0 = 0.f, rs1 = 0.f;
    unsigned short* orow0 = g_dtT + (size_t)jb0 * BSZ;
    unsigned short* orow1 = g_dtT + (size_t)jb1 * BSZ;
#pragma unroll 1
    for (int it = 0; it < 8; it++) {
        int ib = tid + it * 256;
        float li = labels[ib];
        unsigned pos = g_pos[ib];
        int posL = (int)(pos >> 16), posR = (int)(pos & 0xFFFFu);
        // --- two centers, interleaved searches ---
        float dA = c0r - li, dB = c1r - li;
        rs0 += expf(-0.5f * dA * dA);
        rs1 += expf(-0.5f * dB * dB);
        float mirA = c0r + dA, mirB = c1r + dB;
        bool leA = dA > 0.f, leB = dB > 0.f;
        int bA = (int)(mirA * 256.f); bA = bA < 0 ? 0 : (bA > 255 ? 255 : bA);
        while (bA < 255 && (float)(bA + 1) * 0.00390625f <= mirA) bA++;
        while (bA > 0   && (float)bA       * 0.00390625f >  mirA) bA--;
        int bB = (int)(mirB * 256.f); bB = bB < 0 ? 0 : (bB > 255 ? 255 : bB);
        while (bB < 255 && (float)(bB + 1) * 0.00390625f <= mirB) bB++;
        while (bB > 0   && (float)bB       * 0.00390625f >  mirB) bB--;
        int lA = cdf[bA], hA = cdf[bA + 1];
        int lB = cdf[bB], hB = cdf[bB + 1];
#pragma unroll 1
        while (lA < hA || lB < hB) {
            if (lA < hA) { int mid = (lA + hA) >> 1; float v = s[mid];
                           bool p = leA ? (v <= mirA) : (v < mirA);
                           if (p) lA = mid + 1; else hA = mid; }
            if (lB < hB) { int mid = (lB + hB) >> 1; float v = s[mid];
                           bool p = leB ? (v <= mirB) : (v < mirB);
                           if (p) lB = mid + 1; else hB = mid; }
        }
        int LA = leA ? posL : lA;
        int RA = leA ? (lA - 1) : posR;
        int LB = leB ? posL : lB;
        int RB = leB ? (lB - 1) : posR;
        orow0[ib] = (unsigned short)(VIEWS * (BSZ - (RA - LA + 1)));
        orow1[ib] = (unsigned short)(VIEWS * (BSZ - (RB - LB + 1)));
    }
    red[tid] = rs0; __syncthreads();
    for (int st = 128; st > 0; st >>= 1) { if (tid < st) red[tid] += red[tid + st]; __syncthreads(); }
    if (tid == 0) g_S[jb0] = ((float)VIEWS * red[0] - 1.0f) * RSQRT2PI;
    __syncthreads();
    red[tid] = rs1; __syncthreads();
    for (int st = 128; st > 0; st >>= 1) { if (tid < st) red[tid] += red[tid + st]; __syncthreads(); }
    if (tid == 0) g_S[jb1] = ((float)VIEWS * red[0] - 1.0f) * RSQRT2PI;
}

// ---------------- K2b: transpose delta^T -> delta (ushort) -------------------
__global__ void k_transp() {
    __shared__ unsigned short tile[64][72];
    int bx = blockIdx.x & 31, by = blockIdx.x >> 5;
    int r  = threadIdx.x >> 2;
    int c0 = (threadIdx.x & 3) * 16;
    const unsigned short* src = g_dtT + (size_t)(by * 64 + r) * BSZ + bx * 64 + c0;
    *(uint4*)&tile[r][c0]     = *(const uint4*)src;
    *(uint4*)&tile[r][c0 + 8] = *(const uint4*)(src + 8);
    __syncthreads();
    unsigned short ov[16];
#pragma unroll
    for (int k = 0; k < 16; k++) ov[k] = tile[c0 + k][r];
    unsigned short* dst = g_dt + (size_t)(bx * 64 + r) * BSZ + by * 64 + c0;
    *(uint4*)dst       = *(const uint4*)ov;
    *(uint4*)(dst + 8) = *(const uint4*)(ov + 8);
}

// ---------------- K3: fp16 mma.sync GEMM + fused epilogue + fused final ------
__global__ __launch_bounds__(256, 2) void k_main(const float* __restrict__ labels,
                                                 float* __restrict__ out) {
    extern __shared__ __align__(16) char smem[];
    __shared__ float uRow[128], pRow[128], uCol[128], pCol[128];
    __shared__ float slabA[128], slabB[128];
    __shared__ float red[256];
    __shared__ unsigned sLast;
    uint32_t sb = smem_u32(smem);
    int tid = threadIdx.x, wid = tid >> 5, lane = tid & 31;

    int t  = blockIdx.x;
    int bi = (int)((sqrtf(8.f * (float)t + 1.f) - 1.f) * 0.5f);
    while ((bi + 1) * (bi + 2) / 2 <= t) bi++;
    while (bi * (bi + 1) / 2 > t) bi--;
    int bj = t - bi * (bi + 1) / 2;
    int i0 = bi * 128, j0 = bj * 128;
    bool diag = (bi == bj);

    if (tid < 128) {
        uRow[tid] = 0.f; pRow[tid] = 0.f; uCol[tid] = 0.f; pCol[tid] = 0.f;
        slabA[tid] = labels[(i0 + tid) & (BSZ - 1)];
        slabB[tid] = labels[(j0 + tid) & (BSZ - 1)];
    }

    const char* Ab = (const char*)g_FA + (size_t)(i0 >> 7) * 131072;
    const char* Bb = (const char*)g_FB + (size_t)(j0 >> 7) * 131072;

    auto issue = [&](int c, int si) {
        uint32_t stg = sb + (uint32_t)si * STAGE;
        const char* As = Ab + (size_t)c * 16384;
        const char* Bs = Bb + (size_t)c * 16384;
#pragma unroll
        for (int q = 0; q < 4; q++) {
            cpa16(stg + q * 4096 + tid * 16,          As + q * 4096 + tid * 16);
            cpa16(stg + 16384 + q * 4096 + tid * 16,  Bs + q * 4096 + tid * 16);
        }
        CP_COMMIT();
    };

    int wr = wid & 1, wc = wid >> 1;   // warp tile 64 rows x 32 cols

    float acc[4][4][4];
#pragma unroll
    for (int mt = 0; mt < 4; mt++)
#pragma unroll
        for (int nt = 0; nt < 4; nt++)
#pragma unroll
            for (int e = 0; e < 4; e++) acc[mt][nt][e] = 0.f;

    issue(0, 0); issue(1, 1);
    int stc = 0;
#pragma unroll 1
    for (int c = 0; c < NCHUNK; c++) {
        if (c < NCHUNK - 1) { CP_WAIT1(); } else { CP_WAIT0(); }
        __syncthreads();
        if (c + 2 < NCHUNK) {
            int si = stc + 2; if (si >= NSTG) si -= NSTG;
            issue(c + 2, si);
        }
        uint32_t stg = sb + (uint32_t)stc * STAGE;
#pragma unroll
        for (int s = 0; s < 4; s++) {
            int q = s >> 1, ss = s & 1;
            uint32_t a[4][4], b[4][2];
#pragma unroll
            for (int mt = 0; mt < 4; mt++) {
                int tt = wr * 4 + mt;
                uint32_t ad = stg + (uint32_t)(q * 8192 + (tt * 2 + ss) * 512 + lane * 16);
                asm volatile("ld.shared.v4.b32 {%0,%1,%2,%3}, [%4];"
                    : "=r"(a[mt][0]), "=r"(a[mt][1]), "=r"(a[mt][2]), "=r"(a[mt][3]) : "r"(ad));
            }
#pragma unroll
            for (int nt = 0; nt < 4; nt++) {
                int n8 = wc * 4 + nt;
                uint32_t bd = stg + 16384u + (uint32_t)(q * 8192 + (n8 * 2 + ss) * 256 + lane * 8);
                asm volatile("ld.shared.v2.b32 {%0,%1}, [%2];"
                    : "=r"(b[nt][0]), "=r"(b[nt][1]) : "r"(bd));
            }
#pragma unroll
            for (int mt = 0; mt < 4; mt++)
#pragma unroll
                for (int nt = 0; nt < 4; nt++)
                    mma_f16(acc[mt][nt], a[mt], b[nt]);
        }
        stc = (stc == NSTG - 1) ? 0 : stc + 1;
    }

    // ---- fused epilogue ----
    const float invT = 1.0f / TEMP;
    float uR[8], pR[8], uC[8], pC[8];
#pragma unroll
    for (int e = 0; e < 8; e++) { uR[e] = 0.f; pR[e] = 0.f; uC[e] = 0.f; pC[e] = 0.f; }
    int rq = lane >> 2, cq = 2 * (lane & 3);
#pragma unroll
    for (int mt = 0; mt < 4; mt++) {
#pragma unroll
        for (int h = 0; h < 2; h++) {
            int r  = wr * 64 + mt * 16 + rq + h * 8;
            int iB = (i0 + r) & (BSZ - 1);
            float li = slabA[r];
            const unsigned short* dtrow = g_dt  + (size_t)iB * BSZ;
            const unsigned short* dTrow = g_dtT + (size_t)iB * BSZ;
            int ridx = mt * 2 + h;
#pragma unroll
            for (int nt = 0; nt < 4; nt++) {
                int c2  = wc * 32 + nt * 8 + cq;
                int jB2 = (j0 + c2) & (BSZ - 1);
                uint32_t dp  = *(const uint32_t*)(dtrow + jB2);
                uint32_t dTp = *(const uint32_t*)(dTrow + jB2);
#pragma unroll
                for (int e = 0; e < 2; e++) {
                    int cc = c2 + e;
                    float a = acc[mt][nt][h * 2 + e];
                    float x = fmaf(a, invT, -invT);
                    float lj = slabB[cc];
                    float dd = li - lj;
                    float m  = __expf(-0.5f * dd * dd) * RSQRT2PI;
                    float ex = __expf(x);
                    float dv  = (float)((e ? (dp >> 16)  : dp)  & 0xFFFF);
                    float dTv = (float)((e ? (dTp >> 16) : dTp) & 0xFFFF);
                    bool skip = diag && (r == cc);
                    if (!skip) {
                        uR[ridx] = fmaf(ex, dv, uR[ridx]);
                        pR[ridx] = fmaf(m, x, pR[ridx]);
                        if (!diag) {
                            int cidx = nt * 2 + e;
                            uC[cidx] = fmaf(ex, dTv, uC[cidx]);
                            pC[cidx] = fmaf(m, x, pC[cidx]);
                        }
                    }
                }
            }
        }
    }
#pragma unroll
    for (int mt = 0; mt < 4; mt++)
#pragma unroll
        for (int h = 0; h < 2; h++) {
            int r = wr * 64 + mt * 16 + rq + h * 8;
            atomicAdd(&uRow[r], uR[mt * 2 + h]);
            atomicAdd(&pRow[r], pR[mt * 2 + h]);
        }
    if (!diag) {
#pragma unroll
        for (int nt = 0; nt < 4; nt++)
#pragma unroll
            for (int e = 0; e < 2; e++) {
                int cc = wc * 32 + nt * 8 + cq + e;
                atomicAdd(&uCol[cc], uC[nt * 2 + e]);
                atomicAdd(&pCol[cc], pC[nt * 2 + e]);
            }
    }
    __syncthreads();
    if (tid < 128) {
        atomicAdd(&g_u[i0 + tid], uRow[tid]);
        atomicAdd(&g_p[i0 + tid], pRow[tid]);
        if (!diag) {
            atomicAdd(&g_u[j0 + tid], uCol[tid]);
            atomicAdd(&g_p[j0 + tid], pCol[tid]);
        }
    }

    // ---- fused final reduction: last CTA computes the loss ----
    __syncthreads();
    __threadfence();
    if (tid == 0) {
        unsigned old = atomicAdd(&g_ctr, 1u);
        sLast = (old == (unsigned)(NTILES - 1)) ? 1u : 0u;
    }
    __syncthreads();
    if (sLast) {
        __threadfence();
        float sum = 0.f;
        for (int i = tid; i < NTOT; i += 256) {
            sum += g_p[i] / g_S[i & (BSZ - 1)] - logf(g_u[i]);
        }
        red[tid] = sum; __syncthreads();
        for (int st = 128; st > 0; st >>= 1) {
            if (tid < st) red[tid] += red[tid + st];
            __syncthreads();
        }
        if (tid == 0) out[0] = -red[0] / (float)NTOT;
    }
}

// ---------------- entry --------------------------------------------------------
extern "C" void kernel_launch(void* const* d_in, const int* in_sizes, int n_in,
                              void* d_out, int out_size) {
    (void)in_sizes; (void)n_in; (void)out_size;
    const float* feats  = (const float*)d_in[0];
    const float* labels = (const float*)d_in[1];
    float* out = (float*)d_out;

    cudaFuncSetAttribute(k_main, cudaFuncAttributeMaxDynamicSharedMemorySize, DSMEM);

    k_prep  <<<769, 1024>>>(feats, labels);
    k_tab   <<<1024, 256>>>(labels);
    k_transp<<<1024, 256>>>();
    k_main  <<<NTILES, 256, DSMEM>>>(labels, out);
}

// round 15
// speedup vs baseline: 1.0994x; 1.0994x over previous
#include <cuda_runtime.h>
#include <cuda_fp16.h>
#include <cstdint>
#include <math.h>

// ---------------- problem constants ----------------
constexpr int BSZ   = 2048;
constexpr int VIEWS = 2;
constexpr int DIM   = 512;
constexpr int NTOT  = BSZ * VIEWS;          // 4096
constexpr float TEMP = 0.07f;
constexpr float RSQRT2PI = 0.3989422804014327f;

// GEMM tiling (R11-proven): 128x128 CTA tile, 8 warps of 64x32, K-chunks of 64
constexpr int KC = 64;
constexpr int NCHUNK = DIM / KC;             // 8
constexpr int STAGE = 32768;                 // A 16K + B 16K per chunk
constexpr int NSTG = 3;
constexpr int DSMEM = NSTG * STAGE;          // 98304 B -> 2 CTAs/SM

// ---------------- device scratch --------------------
__device__ __align__(16) unsigned g_FA[8192 * 32 * 4];    // 4 MB
__device__ __align__(16) unsigned g_FB[16384 * 32 * 2];   // 4 MB
__device__ __align__(16) unsigned short g_dt [(size_t)BSZ * BSZ];   // delta[i][j], 8 MB
__device__ __align__(16) unsigned short g_dtT[(size_t)BSZ * BSZ];   // delta[j][i], 8 MB
__device__ unsigned g_pos[BSZ];              // (lower_bound(li) << 16) | last_index(<= li)
__device__ int g_cdf[257];                   // cdf[b] = #sorted labels < b/256
__device__ float g_S[BSZ];
__device__ float g_sorted[BSZ];
__device__ float g_u[NTOT];
__device__ float g_p[NTOT];

// ---------------- PTX helpers -----------------------
__device__ __forceinline__ uint32_t smem_u32(const void* p) {
    uint32_t a;
    asm("{ .reg .u64 t; cvta.to.shared.u64 t, %1; cvt.u32.u64 %0, t; }" : "=r"(a) : "l"(p));
    return a;
}
__device__ __forceinline__ void cpa16(uint32_t d, const void* s) {
    asm volatile("cp.async.cg.shared.global [%0], [%1], 16;" :: "r"(d), "l"(s) : "memory");
}
#define CP_COMMIT() asm volatile("cp.async.commit_group;" ::: "memory")
#define CP_WAIT0()  asm volatile("cp.async.wait_group 0;" ::: "memory")
#define CP_WAIT1()  asm volatile("cp.async.wait_group 1;" ::: "memory")
__device__ __forceinline__ void mma_f16(float* c, const uint32_t* a, const uint32_t* b) {
    asm volatile("mma.sync.aligned.m16n8k16.row.col.f32.f16.f16.f32 "
        "{%0,%1,%2,%3}, {%4,%5,%6,%7}, {%8,%9}, {%0,%1,%2,%3};"
        : "+f"(c[0]), "+f"(c[1]), "+f"(c[2]), "+f"(c[3])
        : "r"(a[0]), "r"(a[1]), "r"(a[2]), "r"(a[3]), "r"(b[0]), "r"(b[1]));
}

// ---------------- K0: fp16 scatter (blocks 1..768) + sort/pos/cdf (block 0) --
__device__ __forceinline__ float ld_feat(const float* feats, int row, int col) {
    int b = row & (BSZ - 1), v = row >> 11;
    return feats[(size_t)((b << 1) | v) * DIM + col];
}
__device__ __forceinline__ unsigned pack2(const float* feats, int row, int col) {
    __half2 h = __floats2half2_rn(ld_feat(feats, row, col), ld_feat(feats, row, col + 1));
    return *(unsigned*)&h;
}
__global__ __launch_bounds__(1024) void k_prep(const float* __restrict__ feats,
                                               const float* __restrict__ labels) {
    __shared__ float s[BSZ];
    if (blockIdx.x == 0) {
        // ---- label sort (hybrid bitonic) + positions + CDF ----
        int tid = threadIdx.x;
        int lane = tid & 31, warp = tid >> 5;
        int base = warp * 64;
        int i0 = base + lane, i1 = i0 + 32;
        s[tid] = labels[tid]; s[tid + 1024] = labels[tid + 1024];
        __syncthreads();
        {
            float v0 = s[i0], v1 = s[i1];
#pragma unroll
            for (int k = 2; k <= 64; k <<= 1) {
#pragma unroll
                for (int j = k >> 1; j >= 1; j >>= 1) {
                    if (j == 32) {
                        bool up = ((i0 & k) == 0);
                        float lo = fminf(v0, v1), hi = fmaxf(v0, v1);
                        v0 = up ? lo : hi; v1 = up ? hi : lo;
                    } else {
                        bool up0 = ((i0 & k) == 0), up1 = ((i1 & k) == 0);
                        bool upper = (lane & j) != 0;
                        float p0 = __shfl_xor_sync(0xffffffffu, v0, j);
                        float p1 = __shfl_xor_sync(0xffffffffu, v1, j);
                        v0 = (up0 ^ upper) ? fminf(v0, p0) : fmaxf(v0, p0);
                        v1 = (up1 ^ upper) ? fminf(v1, p1) : fmaxf(v1, p1);
                    }
                }
            }
            s[i0] = v0; s[i1] = v1;
        }
        __syncthreads();
        for (int k = 128; k <= 2048; k <<= 1) {
            for (int j = k >> 1; j >= 64; j >>= 1) {
                for (int i = tid; i < BSZ; i += 1024) {
                    int ixj = i ^ j;
                    if (ixj > i) {
                        bool up = ((i & k) == 0);
                        float a = s[i], b = s[ixj];
                        if ((a > b) == up) { s[i] = b; s[ixj] = a; }
                    }
                }
                __syncthreads();
            }
            {
                float v0 = s[i0], v1 = s[i1];
                bool up = ((i0 & k) == 0);
                float lo = fminf(v0, v1), hi = fmaxf(v0, v1);
                v0 = up ? lo : hi; v1 = up ? hi : lo;
#pragma unroll
                for (int j = 16; j >= 1; j >>= 1) {
                    bool upper = (lane & j) != 0;
                    float p0 = __shfl_xor_sync(0xffffffffu, v0, j);
                    float p1 = __shfl_xor_sync(0xffffffffu, v1, j);
                    v0 = (up ^ upper) ? fminf(v0, p0) : fmaxf(v0, p0);
                    v1 = (up ^ upper) ? fminf(v1, p1) : fmaxf(v1, p1);
                }
                s[i0] = v0; s[i1] = v1;
            }
            __syncthreads();
        }
        g_sorted[tid] = s[tid]; g_sorted[tid + 1024] = s[tid + 1024];
        for (int ib = tid; ib < BSZ; ib += 1024) {
            float li = labels[ib];
            int p = 0, q = 0;
#pragma unroll
            for (int st = 2048; st; st >>= 1) {
                int np = p + st, nq = q + st;
                if (np <= BSZ && s[np - 1] <  li) p = np;
                if (nq <= BSZ && s[nq - 1] <= li) q = nq;
            }
            g_pos[ib] = ((unsigned)p << 16) | (unsigned)(q - 1);
        }
        if (tid <= 256) {
            float thr = (float)tid * 0.00390625f;
            int q = 0;
#pragma unroll
            for (int st = 2048; st; st >>= 1) {
                int nq = q + st;
                if (nq <= BSZ && s[nq - 1] < thr) q = nq;
            }
            g_cdf[tid] = q;
        }
        return;
    }
    // ---- fragment-major fp16 scatter (blocks 1..768) ----
    int tid = (blockIdx.x - 1) * 1024 + threadIdx.x;      // 0..786431
    if (tid < NTOT) { g_u[tid] = 0.f; g_p[tid] = 0.f; }
    int gw = tid >> 5;
    int l  = tid & 31;
    int g  = l >> 2, tg = l & 3;
    if (gw < 8192) {
        int sA = gw & 1, t = (gw >> 1) & 7, ch = (gw >> 4) & 15, rg = gw >> 8;
        int R = rg * 128 + t * 16 + g;
        int C = ch * 32 + sA * 16 + tg * 2;
        uint4 o;
        o.x = pack2(feats, R,     C);
        o.y = pack2(feats, R + 8, C);
        o.z = pack2(feats, R,     C + 8);
        o.w = pack2(feats, R + 8, C + 8);
        ((uint4*)g_FA)[(size_t)gw * 32 + l] = o;
    } else {
        int w2 = gw - 8192;
        int sB = w2 & 1, n8 = (w2 >> 1) & 15, ch = (w2 >> 5) & 15, ng = w2 >> 9;
        int J = ng * 128 + n8 * 8 + g;
        int K = ch * 32 + sB * 16 + tg * 2;
        uint2 o;
        o.x = pack2(feats, J, K);
        o.y = pack2(feats, J, K + 8);
        ((uint2*)g_FB)[(size_t)w2 * 32 + l] = o;
    }
}

// ---------------- K2: delta^T table, 2 rows per block + S row sums -----------
__global__ void k_tab(const float* __restrict__ labels) {
    __shared__ float s[BSZ];
    __shared__ int cdf[257];
    __shared__ float red[256];
    int tid = threadIdx.x;
    int jb0 = blockIdx.x * 2, jb1 = jb0 + 1;
    for (int m = tid; m < BSZ; m += 256) s[m] = g_sorted[m];
    if (tid < 256) cdf[tid] = g_cdf[tid];
    if (tid == 0)  cdf[256] = g_cdf[256];
    __syncthreads();
    float c0r = labels[jb0], c1r = labels[jb1];
    float rs0 = 0.f, rs1 = 0.f;
    unsigned short* orow0 = g_dtT + (size_t)jb0 * BSZ;
    unsigned short* orow1 = g_dtT + (size_t)jb1 * BSZ;
#pragma unroll 1
    for (int it = 0; it < 8; it++) {
        int ib = tid + it * 256;
        float li = labels[ib];
        unsigned pos = g_pos[ib];
        int posL = (int)(pos >> 16), posR = (int)(pos & 0xFFFFu);
        float dA = c0r - li, dB = c1r - li;
        rs0 += expf(-0.5f * dA * dA);
        rs1 += expf(-0.5f * dB * dB);
        float mirA = c0r + dA, mirB = c1r + dB;
        bool leA = dA > 0.f, leB = dB > 0.f;
        int bA = (int)(mirA * 256.f); bA = bA < 0 ? 0 : (bA > 255 ? 255 : bA);
        while (bA < 255 && (float)(bA + 1) * 0.00390625f <= mirA) bA++;
        while (bA > 0   && (float)bA       * 0.00390625f >  mirA) bA--;
        int bB = (int)(mirB * 256.f); bB = bB < 0 ? 0 : (bB > 255 ? 255 : bB);
        while (bB < 255 && (float)(bB + 1) * 0.00390625f <= mirB) bB++;
        while (bB > 0   && (float)bB       * 0.00390625f >  mirB) bB--;
        int lA = cdf[bA], hA = cdf[bA + 1];
        int lB = cdf[bB], hB = cdf[bB + 1];
#pragma unroll 1
        while (lA < hA || lB < hB) {
            if (lA < hA) { int mid = (lA + hA) >> 1; float v = s[mid];
                           bool p = leA ? (v <= mirA) : (v < mirA);
                           if (p) lA = mid + 1; else hA = mid; }
            if (lB < hB) { int mid = (lB + hB) >> 1; float v = s[mid];
                           bool p = leB ? (v <= mirB) : (v < mirB);
                           if (p) lB = mid + 1; else hB = mid; }
        }
        int LA = leA ? posL : lA;
        int RA = leA ? (lA - 1) : posR;
        int LB = leB ? posL : lB;
        int RB = leB ? (lB - 1) : posR;
        orow0[ib] = (unsigned short)(VIEWS * (BSZ - (RA - LA + 1)));
        orow1[ib] = (unsigned short)(VIEWS * (BSZ - (RB - LB + 1)));
    }
    red[tid] = rs0; __syncthreads();
    for (int st = 128; st > 0; st >>= 1) { if (tid < st) red[tid] += red[tid + st]; __syncthreads(); }
    if (tid == 0) g_S[jb0] = ((float)VIEWS * red[0] - 1.0f) * RSQRT2PI;
    __syncthreads();
    red[tid] = rs1; __syncthreads();
    for (int st = 128; st > 0; st >>= 1) { if (tid < st) red[tid] += red[tid + st]; __syncthreads(); }
    if (tid == 0) g_S[jb1] = ((float)VIEWS * red[0] - 1.0f) * RSQRT2PI;
}

// ---------------- K2b: transpose delta^T -> delta (ushort) -------------------
__global__ void k_transp() {
    __shared__ unsigned short tile[64][72];
    int bx = blockIdx.x & 31, by = blockIdx.x >> 5;
    int r  = threadIdx.x >> 2;
    int c0 = (threadIdx.x & 3) * 16;
    const unsigned short* src = g_dtT + (size_t)(by * 64 + r) * BSZ + bx * 64 + c0;
    *(uint4*)&tile[r][c0]     = *(const uint4*)src;
    *(uint4*)&tile[r][c0 + 8] = *(const uint4*)(src + 8);
    __syncthreads();
    unsigned short ov[16];
#pragma unroll
    for (int k = 0; k < 16; k++) ov[k] = tile[c0 + k][r];
    unsigned short* dst = g_dt + (size_t)(bx * 64 + r) * BSZ + by * 64 + c0;
    *(uint4*)dst       = *(const uint4*)ov;
    *(uint4*)(dst + 8) = *(const uint4*)(ov + 8);
}

// ---------------- K3: fp16 mma.sync GEMM + fused epilogue (R11 exact) --------
__global__ __launch_bounds__(256, 2) void k_main(const float* __restrict__ labels) {
    extern __shared__ __align__(16) char smem[];
    __shared__ float uRow[128], pRow[128], uCol[128], pCol[128];
    __shared__ float slabA[128], slabB[128];
    uint32_t sb = smem_u32(smem);
    int tid = threadIdx.x, wid = tid >> 5, lane = tid & 31;

    int t  = blockIdx.x;
    int bi = (int)((sqrtf(8.f * (float)t + 1.f) - 1.f) * 0.5f);
    while ((bi + 1) * (bi + 2) / 2 <= t) bi++;
    while (bi * (bi + 1) / 2 > t) bi--;
    int bj = t - bi * (bi + 1) / 2;
    int i0 = bi * 128, j0 = bj * 128;
    bool diag = (bi == bj);

    if (tid < 128) {
        uRow[tid] = 0.f; pRow[tid] = 0.f; uCol[tid] = 0.f; pCol[tid] = 0.f;
        slabA[tid] = labels[(i0 + tid) & (BSZ - 1)];
        slabB[tid] = labels[(j0 + tid) & (BSZ - 1)];
    }

    const char* Ab = (const char*)g_FA + (size_t)(i0 >> 7) * 131072;
    const char* Bb = (const char*)g_FB + (size_t)(j0 >> 7) * 131072;

    auto issue = [&](int c, int si) {
        uint32_t stg = sb + (uint32_t)si * STAGE;
        const char* As = Ab + (size_t)c * 16384;
        const char* Bs = Bb + (size_t)c * 16384;
#pragma unroll
        for (int q = 0; q < 4; q++) {
            cpa16(stg + q * 4096 + tid * 16,          As + q * 4096 + tid * 16);
            cpa16(stg + 16384 + q * 4096 + tid * 16,  Bs + q * 4096 + tid * 16);
        }
        CP_COMMIT();
    };

    int wr = wid & 1, wc = wid >> 1;   // warp tile 64 rows x 32 cols

    float acc[4][4][4];
#pragma unroll
    for (int mt = 0; mt < 4; mt++)
#pragma unroll
        for (int nt = 0; nt < 4; nt++)
#pragma unroll
            for (int e = 0; e < 4; e++) acc[mt][nt][e] = 0.f;

    issue(0, 0); issue(1, 1);
    int stc = 0;
#pragma unroll 1
    for (int c = 0; c < NCHUNK; c++) {
        if (c < NCHUNK - 1) { CP_WAIT1(); } else { CP_WAIT0(); }
        __syncthreads();
        if (c + 2 < NCHUNK) {
            int si = stc + 2; if (si >= NSTG) si -= NSTG;
            issue(c + 2, si);
        }
        uint32_t stg = sb + (uint32_t)stc * STAGE;
#pragma unroll
        for (int s = 0; s < 4; s++) {
            int q = s >> 1, ss = s & 1;
            uint32_t a[4][4], b[4][2];
#pragma unroll
            for (int mt = 0; mt < 4; mt++) {
                int tt = wr * 4 + mt;
                uint32_t ad = stg + (uint32_t)(q * 8192 + (tt * 2 + ss) * 512 + lane * 16);
                asm volatile("ld.shared.v4.b32 {%0,%1,%2,%3}, [%4];"
                    : "=r"(a[mt][0]), "=r"(a[mt][1]), "=r"(a[mt][2]), "=r"(a[mt][3]) : "r"(ad));
            }
#pragma unroll
            for (int nt = 0; nt < 4; nt++) {
                int n8 = wc * 4 + nt;
                uint32_t bd = stg + 16384u + (uint32_t)(q * 8192 + (n8 * 2 + ss) * 256 + lane * 8);
                asm volatile("ld.shared.v2.b32 {%0,%1}, [%2];"
                    : "=r"(b[nt][0]), "=r"(b[nt][1]) : "r"(bd));
            }
#pragma unroll
            for (int mt = 0; mt < 4; mt++)
#pragma unroll
                for (int nt = 0; nt < 4; nt++)
                    mma_f16(acc[mt][nt], a[mt], b[nt]);
        }
        stc = (stc == NSTG - 1) ? 0 : stc + 1;
    }

    // ---- fused epilogue ----
    const float invT = 1.0f / TEMP;
    float uR[8], pR[8], uC[8], pC[8];
#pragma unroll
    for (int e = 0; e < 8; e++) { uR[e] = 0.f; pR[e] = 0.f; uC[e] = 0.f; pC[e] = 0.f; }
    int rq = lane >> 2, cq = 2 * (lane & 3);
#pragma unroll
    for (int mt = 0; mt < 4; mt++) {
#pragma unroll
        for (int h = 0; h < 2; h++) {
            int r  = wr * 64 + mt * 16 + rq + h * 8;
            int iB = (i0 + r) & (BSZ - 1);
            float li = slabA[r];
            const unsigned short* dtrow = g_dt  + (size_t)iB * BSZ;
            const unsigned short* dTrow = g_dtT + (size_t)iB * BSZ;
            int ridx = mt * 2 + h;
#pragma unroll
            for (int nt = 0; nt < 4; nt++) {
                int c2  = wc * 32 + nt * 8 + cq;
                int jB2 = (j0 + c2) & (BSZ - 1);
                uint32_t dp  = *(const uint32_t*)(dtrow + jB2);
                uint32_t dTp = *(const uint32_t*)(dTrow + jB2);
#pragma unroll
                for (int e = 0; e < 2; e++) {
                    int cc = c2 + e;
                    float a = acc[mt][nt][h * 2 + e];
                    float x = fmaf(a, invT, -invT);
                    float lj = slabB[cc];
                    float dd = li - lj;
                    float m  = __expf(-0.5f * dd * dd) * RSQRT2PI;
                    float ex = __expf(x);
                    float dv  = (float)((e ? (dp >> 16)  : dp)  & 0xFFFF);
                    float dTv = (float)((e ? (dTp >> 16) : dTp) & 0xFFFF);
                    bool skip = diag && (r == cc);
                    if (!skip) {
                        uR[ridx] = fmaf(ex, dv, uR[ridx]);
                        pR[ridx] = fmaf(m, x, pR[ridx]);
                        if (!diag) {
                            int cidx = nt * 2 + e;
                            uC[cidx] = fmaf(ex, dTv, uC[cidx]);
                            pC[cidx] = fmaf(m, x, pC[cidx]);
                        }
                    }
                }
            }
        }
    }
#pragma unroll
    for (int mt = 0; mt < 4; mt++)
#pragma unroll
        for (int h = 0; h < 2; h++) {
            int r = wr * 64 + mt * 16 + rq + h * 8;
            atomicAdd(&uRow[r], uR[mt * 2 + h]);
            atomicAdd(&pRow[r], pR[mt * 2 + h]);
        }
    if (!diag) {
#pragma unroll
        for (int nt = 0; nt < 4; nt++)
#pragma unroll
            for (int e = 0; e < 2; e++) {
                int cc = wc * 32 + nt * 8 + cq + e;
                atomicAdd(&uCol[cc], uC[nt * 2 + e]);
                atomicAdd(&pCol[cc], pC[nt * 2 + e]);
            }
    }
    __syncthreads();
    if (tid < 128) {
        atomicAdd(&g_u[i0 + tid], uRow[tid]);
        atomicAdd(&g_p[i0 + tid], pRow[tid]);
        if (!diag) {
            atomicAdd(&g_u[j0 + tid], uCol[tid]);
            atomicAdd(&g_p[j0 + tid], pCol[tid]);
        }
    }
}

// ---------------- K4: final reduction -----------------------------------------
__global__ void k_final(float* __restrict__ out) {
    __shared__ float red[512];
    int tid = threadIdx.x;
    float sum = 0.f;
    for (int i = tid; i < NTOT; i += 512) {
        float lp = g_p[i] / g_S[i & (BSZ - 1)] - logf(g_u[i]);
        sum += lp;
    }
    red[tid] = sum; __syncthreads();
    for (int st = 256; st > 0; st >>= 1) { if (tid < st) red[tid] += red[tid + st]; __syncthreads(); }
    if (tid == 0) out[0] = -red[0] / (float)NTOT;
}

// ---------------- entry --------------------------------------------------------
extern "C" void kernel_launch(void* const* d_in, const int* in_sizes, int n_in,
                              void* d_out, int out_size) {
    (void)in_sizes; (void)n_in; (void)out_size;
    const float* feats  = (const float*)d_in[0];
    const float* labels = (const float*)d_in[1];
    float* out = (float*)d_out;

    cudaFuncSetAttribute(k_main, cudaFuncAttributeMaxDynamicSharedMemorySize, DSMEM);

    k_prep  <<<769, 1024>>>(feats, labels);
    k_tab   <<<1024, 256>>>(labels);
    k_transp<<<1024, 256>>>();
    k_main  <<<528, 256, DSMEM>>>(labels);
    k_final <<<1, 512>>>(out);
}